// round 15
// baseline (speedup 1.0000x reference)
#include <cuda_runtime.h>
#include <cuda_fp16.h>
#include <cstdint>
#include <cstdio>

// ---------------- problem constants ----------------
#define B_SZ 2
#define S_SZ 1024
#define D_SZ 1024
#define D_INNER 2048
#define HEADDIM 64
#define NHEADS 32
#define D_STATE 64
#define D_CONV 4
#define CONV_DIM (D_INNER + 2 * D_STATE)                 // 2176
#define D_IN_PROJ (2 * D_INNER + 2 * D_STATE + NHEADS)   // 4256
#define H_MLP 8192
#define H_MLP2 4096
#define ROWS (B_SZ * S_SZ)                               // 2048

// ---------------- scratch (device globals; no allocation allowed) ----------------
__device__ float g_zxbcdt[ROWS * D_IN_PROJ];
__device__ float g_xbc[ROWS * CONV_DIM];
__device__ float2 g_dtda[ROWS * NHEADS];
__device__ float g_y[ROWS * D_INNER];
__device__ float g_x1[ROWS * D_SZ];
__device__ float g_part[4 * ROWS * D_SZ];
// fp16 buffers
__device__ __half g_h1[ROWS * H_MLP];
__device__ __half g_xh [ROWS * D_SZ];
__device__ __half g_wip[D_IN_PROJ * D_SZ];
__device__ __half g_wop[D_SZ * D_INNER];
__device__ __half g_wf1[H_MLP * D_SZ];
__device__ __half g_wf2[D_SZ * H_MLP2];
__device__ __half g_yg [ROWS * D_INNER];
__device__ __half g_xn [ROWS * D_SZ];
__device__ __half g_min[ROWS * H_MLP2];

__device__ __forceinline__ float silu_f(float v) {
    return v / (1.f + __expf(-v));
}
__device__ __forceinline__ uint32_t smem_u32(const void* p) {
    uint32_t a;
    asm("{ .reg .u64 t; cvta.to.shared.u64 t, %1; cvt.u32.u64 %0, t; }" : "=r"(a) : "l"(p));
    return a;
}
__device__ __forceinline__ void cp_async16(uint32_t dst, const void* src) {
    asm volatile("cp.async.cg.shared.global [%0], [%1], 16;" :: "r"(dst), "l"(src));
}
#define CP_COMMIT() asm volatile("cp.async.commit_group;" ::: "memory")
#define CP_WAIT(n)  asm volatile("cp.async.wait_group %0;" :: "n"(n) : "memory")

#define HPITCHW 20
#define ASTGW (128 * HPITCHW)
#define STGW  (2 * ASTGW)
#define NSTG  4
#define GEMM_SMEM_BYTES (NSTG * STGW * 4)   // 81920

// ---------------- pipelined fp16 mma.sync GEMM (128x128, optional split-K) ----------------
// B via ldmatrix.x4 (two n-tiles/instr). A fragments split into two halves to
// lower peak register pressure and let MMAs start before all LDSMs issue.
template <int HOUT>
__global__ __launch_bounds__(256, 2) void hgemm_kernel(
    const __half* __restrict__ A, const __half* __restrict__ W,
    const float* __restrict__ addend, void* __restrict__ Cv_,
    int M, int N, int K, int kchunk)
{
    extern __shared__ uint32_t sm[];
    const uint32_t sb = smem_u32(sm);

    const int tid = threadIdx.x;
    const int bm = blockIdx.y * 128;
    const int bn = blockIdx.x * 128;
    const int kbeg = blockIdx.z * kchunk;
    const bool partial = (gridDim.z > 1);

    const int warp = tid >> 5;
    const int lane = tid & 31;
    const int g  = lane >> 2;
    const int t4 = lane & 3;
    const int warp_m = (warp >> 2) * 64;
    const int warp_n = (warp & 3) * 32;

    const uint32_t a_off =
        ((uint32_t)(warp_m + (lane & 7) + ((lane >> 3) & 1) * 8) * HPITCHW
         + ((lane >> 4) & 1) * 4) * 4;
    const uint32_t b_off4 =
        ((uint32_t)(warp_n + (lane & 7) + ((lane >> 4) & 1) * 8) * HPITCHW
         + ((lane >> 3) & 1) * 4) * 4;

    const int lr = tid >> 2;
    const int q  = tid & 3;

    const __half* Ap0 = A + (size_t)(bm + lr) * K + kbeg + q * 8;
    const __half* Ap1 = A + (size_t)(bm + 64 + lr) * K + kbeg + q * 8;
    int wr0 = bn + lr;      if (wr0 > N - 1) wr0 = N - 1;
    int wr1 = bn + 64 + lr; if (wr1 > N - 1) wr1 = N - 1;
    const __half* Wp0 = W + (size_t)wr0 * K + kbeg + q * 8;
    const __half* Wp1 = W + (size_t)wr1 * K + kbeg + q * 8;

    const uint32_t d0 = (uint32_t)lr * 80 + q * 16;
    const uint32_t d1 = d0 + 64 * 80;
    const int T = kchunk / 32;

    float acc[4][4][4];
#pragma unroll
    for (int i = 0; i < 4; i++)
#pragma unroll
        for (int j = 0; j < 4; j++)
#pragma unroll
            for (int r = 0; r < 4; r++) acc[i][j][r] = 0.f;

    auto load_stage = [&](int j) {
        if (j < T) {
            const uint32_t base = sb + (j & (NSTG - 1)) * (STGW * 4);
            const int ko = j * 32;
            cp_async16(base + d0, Ap0 + ko);
            cp_async16(base + d1, Ap1 + ko);
            cp_async16(base + ASTGW * 4 + d0, Wp0 + ko);
            cp_async16(base + ASTGW * 4 + d1, Wp1 + ko);
        }
        CP_COMMIT();
    };

    load_stage(0);
    load_stage(1);
    load_stage(2);

    for (int kt = 0; kt < T; kt++) {
        CP_WAIT(2);
        __syncthreads();
        load_stage(kt + 3);

        const uint32_t sA = sb + (kt & (NSTG - 1)) * (STGW * 4);
        const uint32_t sB = sA + ASTGW * 4;
#pragma unroll
        for (int kw = 0; kw < 16; kw += 8) {
            uint32_t bf[4][2];
#pragma unroll
            for (int ntp = 0; ntp < 2; ntp++) {
                const uint32_t addr = sB + b_off4 + (uint32_t)(ntp * 16 * HPITCHW + kw) * 4;
                asm volatile(
                    "ldmatrix.sync.aligned.m8n8.x4.shared.b16 {%0,%1,%2,%3}, [%4];"
                    : "=r"(bf[2 * ntp][0]), "=r"(bf[2 * ntp][1]),
                      "=r"(bf[2 * ntp + 1][0]), "=r"(bf[2 * ntp + 1][1])
                    : "r"(addr));
            }
            // first half of A fragments, then their MMAs; then second half.
#pragma unroll
            for (int half = 0; half < 2; half++) {
                uint32_t af[2][4];
#pragma unroll
                for (int m2 = 0; m2 < 2; m2++) {
                    const int mt = half * 2 + m2;
                    const uint32_t addr = sA + a_off + (uint32_t)(mt * 16 * HPITCHW + kw) * 4;
                    asm volatile(
                        "ldmatrix.sync.aligned.m8n8.x4.shared.b16 {%0,%1,%2,%3}, [%4];"
                        : "=r"(af[m2][0]), "=r"(af[m2][1]), "=r"(af[m2][2]), "=r"(af[m2][3])
                        : "r"(addr));
                }
#pragma unroll
                for (int m2 = 0; m2 < 2; m2++) {
                    const int mt = half * 2 + m2;
#pragma unroll
                    for (int nt = 0; nt < 4; nt++) {
                        asm volatile(
                            "mma.sync.aligned.m16n8k16.row.col.f32.f16.f16.f32 "
                            "{%0,%1,%2,%3}, {%4,%5,%6,%7}, {%8,%9}, {%0,%1,%2,%3};"
                            : "+f"(acc[mt][nt][0]), "+f"(acc[mt][nt][1]),
                              "+f"(acc[mt][nt][2]), "+f"(acc[mt][nt][3])
                            : "r"(af[m2][0]), "r"(af[m2][1]), "r"(af[m2][2]), "r"(af[m2][3]),
                              "r"(bf[nt][0]), "r"(bf[nt][1]));
                    }
                }
            }
        }
    }

#pragma unroll
    for (int mt = 0; mt < 4; mt++) {
        const int row0 = bm + warp_m + mt * 16 + g;
#pragma unroll
        for (int nt = 0; nt < 4; nt++) {
            const int col = bn + warp_n + nt * 8 + 2 * t4;
            if (col < N) {
                if (HOUT) {
                    __half* Ch = (__half*)Cv_;
                    *reinterpret_cast<__half2*>(&Ch[(size_t)row0 * N + col]) =
                        __floats2half2_rn(acc[mt][nt][0], acc[mt][nt][1]);
                    *reinterpret_cast<__half2*>(&Ch[(size_t)(row0 + 8) * N + col]) =
                        __floats2half2_rn(acc[mt][nt][2], acc[mt][nt][3]);
                } else {
                    float* Cf = (float*)Cv_;
                    float* Co = partial ? (Cf + (size_t)blockIdx.z * M * N) : Cf;
                    float2 v0 = make_float2(acc[mt][nt][0], acc[mt][nt][1]);
                    float2 v1 = make_float2(acc[mt][nt][2], acc[mt][nt][3]);
                    if (!partial && addend) {
                        const float2 a0 = *reinterpret_cast<const float2*>(&addend[(size_t)row0 * N + col]);
                        const float2 a1 = *reinterpret_cast<const float2*>(&addend[(size_t)(row0 + 8) * N + col]);
                        v0.x += a0.x; v0.y += a0.y;
                        v1.x += a1.x; v1.y += a1.y;
                    }
                    *reinterpret_cast<float2*>(&Co[(size_t)row0 * N + col]) = v0;
                    *reinterpret_cast<float2*>(&Co[(size_t)(row0 + 8) * N + col]) = v1;
                }
            }
        }
    }
}

// ---------------- fused reduce2 + residual + rms ----------------
__global__ __launch_bounds__(256) void reduce2_rms_kernel(const float* __restrict__ xin,
                                                          const float* __restrict__ w)
{
    const int row = blockIdx.x;
    const int tid = threadIdx.x;
    const float* xr = xin    + (size_t)row * D_SZ;
    const float* p0 = g_part + (size_t)row * D_SZ;
    const float* p1 = g_part + (size_t)(ROWS + row) * D_SZ;
    float* x1r = g_x1 + (size_t)row * D_SZ;

    float vals[4];
    float ss = 0.f;
#pragma unroll
    for (int i = 0; i < 4; i++) {
        const int c = tid + i * 256;
        float v = xr[c] + p0[c] + p1[c];
        x1r[c] = v;
        vals[i] = v;
        ss = fmaf(v, v, ss);
    }
    __shared__ float red[32];
#pragma unroll
    for (int o = 16; o > 0; o >>= 1) ss += __shfl_down_sync(0xffffffffu, ss, o);
    if ((tid & 31) == 0) red[tid >> 5] = ss;
    __syncthreads();
    if (tid < 32) {
        float v = (tid < 8) ? red[tid] : 0.f;
#pragma unroll
        for (int o = 4; o > 0; o >>= 1) v += __shfl_down_sync(0xffffffffu, v, o);
        if (tid == 0) red[0] = v;
    }
    __syncthreads();
    const float inv = rsqrtf(red[0] / (float)D_SZ + 1e-5f);
#pragma unroll
    for (int i = 0; i < 4; i++) {
        const int c = tid + i * 256;
        g_xn[(size_t)row * D_SZ + c] = __float2half_rn(vals[i] * inv * w[c]);
    }
}

// ---------------- split-K=4 reduction ----------------
__global__ void reduce4_kernel(const float* __restrict__ addend,
                               float* __restrict__ out, int n4)
{
    const int i = blockIdx.x * blockDim.x + threadIdx.x;
    if (i >= n4) return;
    float4 v = reinterpret_cast<const float4*>(addend)[i];
#pragma unroll
    for (int z = 0; z < 4; z++) {
        const float4 p = reinterpret_cast<const float4*>(g_part + (size_t)z * ROWS * D_SZ)[i];
        v.x += p.x; v.y += p.y; v.z += p.z; v.w += p.w;
    }
    reinterpret_cast<float4*>(out)[i] = v;
}

// ---------------- fp32 -> fp16 conversion (MLP=4) ----------------
__global__ void cvt_h_kernel(const float* __restrict__ in, __half* __restrict__ out, int n4)
{
    const int stride = gridDim.x * blockDim.x;
    int i = blockIdx.x * blockDim.x + threadIdx.x;
#pragma unroll
    for (int r = 0; r < 4; r++) {
        if (i < n4) {
            float4 v = reinterpret_cast<const float4*>(in)[i];
            __half2 h0 = __floats2half2_rn(v.x, v.y);
            __half2 h1 = __floats2half2_rn(v.z, v.w);
            *reinterpret_cast<uint2*>(out + (size_t)i * 4) =
                make_uint2(*reinterpret_cast<uint32_t*>(&h0), *reinterpret_cast<uint32_t*>(&h1));
        }
        i += stride;
    }
}
#define CVT_GRID(n4) (((n4) + 4 * 256 - 1) / (4 * 256))

// ---------------- causal depthwise conv (k=4) + bias + silu, vectorized ----------------
// grid = ROWS blocks, 544 threads (17 warps); thread = 4 adjacent channels. No division.
__global__ __launch_bounds__(544) void conv_silu_kernel(const float* __restrict__ conv_w,
                                                        const float* __restrict__ conv_b)
{
    const int bs = blockIdx.x;          // 0..ROWS-1
    const int s  = bs & (S_SZ - 1);
    const int c  = threadIdx.x * 4;     // channel base, 0..2172

    // all 4 taps of each channel in one float4
    const float4 w0 = __ldg(reinterpret_cast<const float4*>(conv_w) + (c + 0));
    const float4 w1 = __ldg(reinterpret_cast<const float4*>(conv_w) + (c + 1));
    const float4 w2 = __ldg(reinterpret_cast<const float4*>(conv_w) + (c + 2));
    const float4 w3 = __ldg(reinterpret_cast<const float4*>(conv_w) + (c + 3));
    float4 acc = __ldg(reinterpret_cast<const float4*>(conv_b) + threadIdx.x);

    const float* base = g_zxbcdt + (size_t)bs * D_IN_PROJ + D_INNER + c;
#pragma unroll
    for (int k = 0; k < D_CONV; k++) {
        const int off = k - (D_CONV - 1);        // -3..0
        if (s + off >= 0) {
            const float4 v = *reinterpret_cast<const float4*>(base + (ptrdiff_t)off * D_IN_PROJ);
            acc.x = fmaf(v.x, (&w0.x)[k], acc.x);
            acc.y = fmaf(v.y, (&w1.x)[k], acc.y);
            acc.z = fmaf(v.z, (&w2.x)[k], acc.z);
            acc.w = fmaf(v.w, (&w3.x)[k], acc.w);
        }
    }
    acc.x = silu_f(acc.x);
    acc.y = silu_f(acc.y);
    acc.z = silu_f(acc.z);
    acc.w = silu_f(acc.w);
    *reinterpret_cast<float4*>(g_xbc + (size_t)bs * CONV_DIM + c) = acc;
}

// ---------------- dt/dA packed ----------------
__global__ void dt_kernel(const float* __restrict__ dt_bias,
                          const float* __restrict__ A_log)
{
    const int idx = blockIdx.x * blockDim.x + threadIdx.x;
    if (idx >= ROWS * NHEADS) return;
    const int h = idx & (NHEADS - 1);
    const int r = idx >> 5;
    float x = g_zxbcdt[(size_t)r * D_IN_PROJ + (D_IN_PROJ - NHEADS) + h] + dt_bias[h];
    float dt = (x > 20.f) ? x : log1pf(expf(x));
    g_dtda[idx] = make_float2(dt, expf(-expf(A_log[h]) * dt));
}

// ---------------- SSM scan (round-7 proven config) ----------------
__global__ __launch_bounds__(512, 2) void scan_kernel()
{
    const int pc   = blockIdx.x & 3;
    const int h    = (blockIdx.x >> 2) & (NHEADS - 1);
    const int b    = blockIdx.x >> 7;
    const int w    = threadIdx.x >> 5;
    const int lane = threadIdx.x & 31;
    const int p    = pc * 16 + w;

    const float* rb = g_xbc + (size_t)(b * S_SZ) * CONV_DIM;
    const int xoff = h * HEADDIM + p;
    const float2* dd = g_dtda + (size_t)(b * S_SZ) * NHEADS + h;
    float* yo = g_y + ((size_t)b * S_SZ * NHEADS + h) * HEADDIM + p;

    float h0 = 0.f, h1 = 0.f;

    float2 Bv[2][4], Cv[2][4], Dv[2][4];
    float  Xv[2][4];

    auto ldgrp = [&](int grp, int buf) {
#pragma unroll
        for (int i = 0; i < 4; i++) {
            const int s = grp * 4 + i;
            const float* row = rb + (size_t)s * CONV_DIM;
            Bv[buf][i] = __ldg(reinterpret_cast<const float2*>(row + D_INNER) + lane);
            Cv[buf][i] = __ldg(reinterpret_cast<const float2*>(row + D_INNER + D_STATE) + lane);
            Xv[buf][i] = __ldg(row + xoff);
            Dv[buf][i] = __ldg(dd + (size_t)s * NHEADS);
        }
    };

    ldgrp(0, 0);
    const int NG = S_SZ / 4;
    for (int grp = 0; grp < NG; grp++) {
        const int cur = grp & 1;
        if (grp + 1 < NG) ldgrp(grp + 1, cur ^ 1);

        float part[4];
#pragma unroll
        for (int i = 0; i < 4; i++) {
            const float c = Dv[cur][i].x * Xv[cur][i];
            h0 = fmaf(h0, Dv[cur][i].y, c * Bv[cur][i].x);
            h1 = fmaf(h1, Dv[cur][i].y, c * Bv[cur][i].y);
            part[i] = fmaf(h1, Cv[cur][i].y, h0 * Cv[cur][i].x);
        }
#pragma unroll
        for (int o = 16; o > 0; o >>= 1) {
#pragma unroll
            for (int i = 0; i < 4; i++)
                part[i] += __shfl_xor_sync(0xffffffffu, part[i], o);
        }
        if (lane == 0) {
#pragma unroll
            for (int i = 0; i < 4; i++)
                yo[(size_t)(grp * 4 + i) * (NHEADS * HEADDIM)] = part[i];
        }
    }
}

// ---------------- gate: yg = rms((y + D*xs) * silu(z)) * w  -> fp16 ----------------
__global__ __launch_bounds__(256) void gate_rms_kernel(const float* __restrict__ Dp,
                                                       const float* __restrict__ normw)
{
    const int row = blockIdx.x;
    const int tid = threadIdx.x;

    const float* yr = g_y      + (size_t)row * D_INNER;
    const float* xb = g_xbc    + (size_t)row * CONV_DIM;
    const float* zr = g_zxbcdt + (size_t)row * D_IN_PROJ;

    float vals[8];
    float ss = 0.f;
#pragma unroll
    for (int i = 0; i < 8; i++) {
        const int c = tid + i * 256;
        float v = fmaf(Dp[c >> 6], xb[c], yr[c]);
        v *= silu_f(zr[c]);
        vals[i] = v;
        ss = fmaf(v, v, ss);
    }
    __shared__ float red[32];
#pragma unroll
    for (int o = 16; o > 0; o >>= 1) ss += __shfl_down_sync(0xffffffffu, ss, o);
    if ((tid & 31) == 0) red[tid >> 5] = ss;
    __syncthreads();
    if (tid < 32) {
        float v = (tid < 8) ? red[tid] : 0.f;
#pragma unroll
        for (int o = 4; o > 0; o >>= 1) v += __shfl_down_sync(0xffffffffu, v, o);
        if (tid == 0) red[0] = v;
    }
    __syncthreads();
    const float inv = rsqrtf(red[0] / (float)D_INNER + 1e-5f);
#pragma unroll
    for (int i = 0; i < 8; i++) {
        const int c = tid + i * 256;
        g_yg[(size_t)row * D_INNER + c] = __float2half_rn(vals[i] * inv * normw[c]);
    }
}

// ---------------- GLU (fp16, vectorized) ----------------
__global__ void glu_kernel()
{
    const int idx = blockIdx.x * blockDim.x + threadIdx.x;
    if (idx >= ROWS * H_MLP2 / 2) return;
    const int j2 = idx % (H_MLP2 / 2);
    const int r  = idx / (H_MLP2 / 2);
    const __half2 a2 = *reinterpret_cast<const __half2*>(&g_h1[(size_t)r * H_MLP + j2 * 2]);
    const __half2 g2 = *reinterpret_cast<const __half2*>(&g_h1[(size_t)r * H_MLP + H_MLP2 + j2 * 2]);
    const float2 af = __half22float2(a2);
    const float2 gf = __half22float2(g2);
    *reinterpret_cast<__half2*>(&g_min[(size_t)r * H_MLP2 + j2 * 2]) =
        __floats2half2_rn(af.x * silu_f(gf.x), af.y * silu_f(gf.y));
}

// ---------------- launch ----------------
extern "C" void kernel_launch(void* const* d_in, const int* in_sizes, int n_in,
                              void* d_out, int out_size)
{
    const float* x          = (const float*)d_in[0];
    const float* in_proj_w  = (const float*)d_in[1];
    const float* conv_w     = (const float*)d_in[2];
    const float* conv_b     = (const float*)d_in[3];
    const float* dt_bias    = (const float*)d_in[4];
    const float* A_log      = (const float*)d_in[5];
    const float* Dp         = (const float*)d_in[6];
    const float* ssm_norm_w = (const float*)d_in[7];
    const float* out_proj_w = (const float*)d_in[8];
    const float* rms_w      = (const float*)d_in[9];
    const float* fc1_w      = (const float*)d_in[10];
    const float* fc2_w      = (const float*)d_in[11];
    float* out = (float*)d_out;

    float *p_zx, *p_x1, *p_part;
    __half *p_h1, *p_xh, *p_wip, *p_wop, *p_wf1, *p_wf2, *p_yg, *p_xn, *p_min;
    cudaGetSymbolAddress((void**)&p_zx,  g_zxbcdt);
    cudaGetSymbolAddress((void**)&p_x1,  g_x1);
    cudaGetSymbolAddress((void**)&p_part, g_part);
    cudaGetSymbolAddress((void**)&p_h1,  g_h1);
    cudaGetSymbolAddress((void**)&p_xh,  g_xh);
    cudaGetSymbolAddress((void**)&p_wip, g_wip);
    cudaGetSymbolAddress((void**)&p_wop, g_wop);
    cudaGetSymbolAddress((void**)&p_wf1, g_wf1);
    cudaGetSymbolAddress((void**)&p_wf2, g_wf2);
    cudaGetSymbolAddress((void**)&p_yg,  g_yg);
    cudaGetSymbolAddress((void**)&p_xn,  g_xn);
    cudaGetSymbolAddress((void**)&p_min, g_min);

    cudaFuncSetAttribute(hgemm_kernel<0>,
                         cudaFuncAttributeMaxDynamicSharedMemorySize, GEMM_SMEM_BYTES);
    cudaFuncSetAttribute(hgemm_kernel<1>,
                         cudaFuncAttributeMaxDynamicSharedMemorySize, GEMM_SMEM_BYTES);

    // in_proj is our 4th launch so ncu (-s 5 -c 1) profiles it.
    cvt_h_kernel<<<CVT_GRID(ROWS * D_SZ / 4), 256>>>(x, p_xh, ROWS * D_SZ / 4);                  // 1
    cvt_h_kernel<<<CVT_GRID(D_IN_PROJ * D_SZ / 4), 256>>>(in_proj_w, p_wip, D_IN_PROJ * D_SZ / 4); // 2
    cvt_h_kernel<<<CVT_GRID(D_SZ * D_INNER / 4), 256>>>(out_proj_w, p_wop, D_SZ * D_INNER / 4);    // 3

    // 4) in_proj: zxbcdt[2048,4256] = xh @ wip^T
    {
        dim3 grid((D_IN_PROJ + 127) / 128, ROWS / 128, 1);
        hgemm_kernel<0><<<grid, 256, GEMM_SMEM_BYTES>>>(p_xh, p_wip, nullptr, p_zx,
                                                        ROWS, D_IN_PROJ, D_SZ, D_SZ);
    }

    cvt_h_kernel<<<CVT_GRID(H_MLP * D_SZ / 4), 256>>>(fc1_w, p_wf1, H_MLP * D_SZ / 4);           // 5
    cvt_h_kernel<<<CVT_GRID(D_SZ * H_MLP2 / 4), 256>>>(fc2_w, p_wf2, D_SZ * H_MLP2 / 4);         // 6

    // dt/dA (packed)
    dt_kernel<<<(ROWS * NHEADS + 255) / 256, 256>>>(dt_bias, A_log);
    // conv + silu (vectorized, no division)
    conv_silu_kernel<<<ROWS, CONV_DIM / 4>>>(conv_w, conv_b);
    // scan
    scan_kernel<<<B_SZ * NHEADS * 4, 512>>>();
    // gate + rms(ssm_norm)
    gate_rms_kernel<<<ROWS, 256>>>(Dp, ssm_norm_w);
    // out_proj split-K=2, then fused: x1 = x + p0 + p1, xn = rms(x1)*w
    {
        dim3 grid(D_SZ / 128, ROWS / 128, 2);
        hgemm_kernel<0><<<grid, 256, GEMM_SMEM_BYTES>>>(p_yg, p_wop, nullptr, p_part,
                                                        ROWS, D_SZ, D_INNER, D_INNER / 2);
        reduce2_rms_kernel<<<ROWS, 256>>>(x, rms_w);
    }
    // fc1: h1 = xn @ wf1^T  (fp16 output)
    {
        dim3 grid(H_MLP / 128, ROWS / 128, 1);
        hgemm_kernel<1><<<grid, 256, GEMM_SMEM_BYTES>>>(p_xn, p_wf1, nullptr, p_h1,
                                                        ROWS, H_MLP, D_SZ, D_SZ);
    }
    // GLU (fp16, vectorized)
    glu_kernel<<<(ROWS * H_MLP2 / 2 + 255) / 256, 256>>>();
    // fc2 split-K=4, then out = x1 + sum parts
    {
        dim3 grid(D_SZ / 128, ROWS / 128, 4);
        hgemm_kernel<0><<<grid, 256, GEMM_SMEM_BYTES>>>(p_min, p_wf2, nullptr, p_part,
                                                        ROWS, D_SZ, H_MLP2, H_MLP2 / 4);
        reduce4_kernel<<<(ROWS * D_SZ / 4 + 255) / 256, 256>>>(p_x1, out, ROWS * D_SZ / 4);
    }
}

// round 16
// speedup vs baseline: 1.0156x; 1.0156x over previous
#include <cuda_runtime.h>
#include <cuda_fp16.h>
#include <cstdint>
#include <cstdio>

// ---------------- problem constants ----------------
#define B_SZ 2
#define S_SZ 1024
#define D_SZ 1024
#define D_INNER 2048
#define HEADDIM 64
#define NHEADS 32
#define D_STATE 64
#define D_CONV 4
#define CONV_DIM (D_INNER + 2 * D_STATE)                 // 2176
#define D_IN_PROJ (2 * D_INNER + 2 * D_STATE + NHEADS)   // 4256
#define H_MLP 8192
#define H_MLP2 4096
#define ROWS (B_SZ * S_SZ)                               // 2048

// ---------------- scratch (device globals; no allocation allowed) ----------------
__device__ float g_zxbcdt[ROWS * D_IN_PROJ];
__device__ float g_xbc[ROWS * CONV_DIM];
__device__ float2 g_dtda[ROWS * NHEADS];
__device__ float g_y[ROWS * D_INNER];
__device__ float g_x1[ROWS * D_SZ];
__device__ float g_part[4 * ROWS * D_SZ];
// fp16 buffers
__device__ __half g_h1[ROWS * H_MLP];
__device__ __half g_xh [ROWS * D_SZ];
__device__ __half g_wip[D_IN_PROJ * D_SZ];
__device__ __half g_wop[D_SZ * D_INNER];
__device__ __half g_wf1[H_MLP * D_SZ];
__device__ __half g_wf2[D_SZ * H_MLP2];
__device__ __half g_yg [ROWS * D_INNER];
__device__ __half g_xn [ROWS * D_SZ];
__device__ __half g_min[ROWS * H_MLP2];

__device__ __forceinline__ float silu_f(float v) {
    return v / (1.f + __expf(-v));
}
__device__ __forceinline__ uint32_t smem_u32(const void* p) {
    uint32_t a;
    asm("{ .reg .u64 t; cvta.to.shared.u64 t, %1; cvt.u32.u64 %0, t; }" : "=r"(a) : "l"(p));
    return a;
}
__device__ __forceinline__ void cp_async16(uint32_t dst, const void* src) {
    asm volatile("cp.async.cg.shared.global [%0], [%1], 16;" :: "r"(dst), "l"(src));
}
#define CP_COMMIT() asm volatile("cp.async.commit_group;" ::: "memory")
#define CP_WAIT(n)  asm volatile("cp.async.wait_group %0;" :: "n"(n) : "memory")

#define HPITCHW 20
#define ASTGW (128 * HPITCHW)
#define STGW  (2 * ASTGW)
#define NSTG  4
#define GEMM_SMEM_BYTES (NSTG * STGW * 4)   // 81920

// ---------------- pipelined fp16 mma.sync GEMM (128x128, optional split-K) ----------------
// Round-14 proven inner loop: batched af[4] ldmatrix.x4 + B via ldmatrix.x4
// (two n-tiles per instruction), then 16 MMAs.
template <int HOUT>
__global__ __launch_bounds__(256, 2) void hgemm_kernel(
    const __half* __restrict__ A, const __half* __restrict__ W,
    const float* __restrict__ addend, void* __restrict__ Cv_,
    int M, int N, int K, int kchunk)
{
    extern __shared__ uint32_t sm[];
    const uint32_t sb = smem_u32(sm);

    const int tid = threadIdx.x;
    const int bm = blockIdx.y * 128;
    const int bn = blockIdx.x * 128;
    const int kbeg = blockIdx.z * kchunk;
    const bool partial = (gridDim.z > 1);

    const int warp = tid >> 5;
    const int lane = tid & 31;
    const int g  = lane >> 2;
    const int t4 = lane & 3;
    const int warp_m = (warp >> 2) * 64;
    const int warp_n = (warp & 3) * 32;

    const uint32_t a_off =
        ((uint32_t)(warp_m + (lane & 7) + ((lane >> 3) & 1) * 8) * HPITCHW
         + ((lane >> 4) & 1) * 4) * 4;
    const uint32_t b_off4 =
        ((uint32_t)(warp_n + (lane & 7) + ((lane >> 4) & 1) * 8) * HPITCHW
         + ((lane >> 3) & 1) * 4) * 4;

    const int lr = tid >> 2;
    const int q  = tid & 3;

    const __half* Ap0 = A + (size_t)(bm + lr) * K + kbeg + q * 8;
    const __half* Ap1 = A + (size_t)(bm + 64 + lr) * K + kbeg + q * 8;
    int wr0 = bn + lr;      if (wr0 > N - 1) wr0 = N - 1;
    int wr1 = bn + 64 + lr; if (wr1 > N - 1) wr1 = N - 1;
    const __half* Wp0 = W + (size_t)wr0 * K + kbeg + q * 8;
    const __half* Wp1 = W + (size_t)wr1 * K + kbeg + q * 8;

    const uint32_t d0 = (uint32_t)lr * 80 + q * 16;
    const uint32_t d1 = d0 + 64 * 80;
    const int T = kchunk / 32;

    float acc[4][4][4];
#pragma unroll
    for (int i = 0; i < 4; i++)
#pragma unroll
        for (int j = 0; j < 4; j++)
#pragma unroll
            for (int r = 0; r < 4; r++) acc[i][j][r] = 0.f;

    auto load_stage = [&](int j) {
        if (j < T) {
            const uint32_t base = sb + (j & (NSTG - 1)) * (STGW * 4);
            const int ko = j * 32;
            cp_async16(base + d0, Ap0 + ko);
            cp_async16(base + d1, Ap1 + ko);
            cp_async16(base + ASTGW * 4 + d0, Wp0 + ko);
            cp_async16(base + ASTGW * 4 + d1, Wp1 + ko);
        }
        CP_COMMIT();
    };

    load_stage(0);
    load_stage(1);
    load_stage(2);

    for (int kt = 0; kt < T; kt++) {
        CP_WAIT(2);
        __syncthreads();
        load_stage(kt + 3);

        const uint32_t sA = sb + (kt & (NSTG - 1)) * (STGW * 4);
        const uint32_t sB = sA + ASTGW * 4;
#pragma unroll
        for (int kw = 0; kw < 16; kw += 8) {
            uint32_t af[4][4];
            uint32_t bf[4][2];
#pragma unroll
            for (int mt = 0; mt < 4; mt++) {
                const uint32_t addr = sA + a_off + (uint32_t)(mt * 16 * HPITCHW + kw) * 4;
                asm volatile(
                    "ldmatrix.sync.aligned.m8n8.x4.shared.b16 {%0,%1,%2,%3}, [%4];"
                    : "=r"(af[mt][0]), "=r"(af[mt][1]), "=r"(af[mt][2]), "=r"(af[mt][3])
                    : "r"(addr));
            }
#pragma unroll
            for (int ntp = 0; ntp < 2; ntp++) {
                const uint32_t addr = sB + b_off4 + (uint32_t)(ntp * 16 * HPITCHW + kw) * 4;
                asm volatile(
                    "ldmatrix.sync.aligned.m8n8.x4.shared.b16 {%0,%1,%2,%3}, [%4];"
                    : "=r"(bf[2 * ntp][0]), "=r"(bf[2 * ntp][1]),
                      "=r"(bf[2 * ntp + 1][0]), "=r"(bf[2 * ntp + 1][1])
                    : "r"(addr));
            }
#pragma unroll
            for (int mt = 0; mt < 4; mt++)
#pragma unroll
                for (int nt = 0; nt < 4; nt++) {
                    asm volatile(
                        "mma.sync.aligned.m16n8k16.row.col.f32.f16.f16.f32 "
                        "{%0,%1,%2,%3}, {%4,%5,%6,%7}, {%8,%9}, {%0,%1,%2,%3};"
                        : "+f"(acc[mt][nt][0]), "+f"(acc[mt][nt][1]),
                          "+f"(acc[mt][nt][2]), "+f"(acc[mt][nt][3])
                        : "r"(af[mt][0]), "r"(af[mt][1]), "r"(af[mt][2]), "r"(af[mt][3]),
                          "r"(bf[nt][0]), "r"(bf[nt][1]));
                }
        }
    }

#pragma unroll
    for (int mt = 0; mt < 4; mt++) {
        const int row0 = bm + warp_m + mt * 16 + g;
#pragma unroll
        for (int nt = 0; nt < 4; nt++) {
            const int col = bn + warp_n + nt * 8 + 2 * t4;
            if (col < N) {
                if (HOUT) {
                    __half* Ch = (__half*)Cv_;
                    *reinterpret_cast<__half2*>(&Ch[(size_t)row0 * N + col]) =
                        __floats2half2_rn(acc[mt][nt][0], acc[mt][nt][1]);
                    *reinterpret_cast<__half2*>(&Ch[(size_t)(row0 + 8) * N + col]) =
                        __floats2half2_rn(acc[mt][nt][2], acc[mt][nt][3]);
                } else {
                    float* Cf = (float*)Cv_;
                    float* Co = partial ? (Cf + (size_t)blockIdx.z * M * N) : Cf;
                    float2 v0 = make_float2(acc[mt][nt][0], acc[mt][nt][1]);
                    float2 v1 = make_float2(acc[mt][nt][2], acc[mt][nt][3]);
                    if (!partial && addend) {
                        const float2 a0 = *reinterpret_cast<const float2*>(&addend[(size_t)row0 * N + col]);
                        const float2 a1 = *reinterpret_cast<const float2*>(&addend[(size_t)(row0 + 8) * N + col]);
                        v0.x += a0.x; v0.y += a0.y;
                        v1.x += a1.x; v1.y += a1.y;
                    }
                    *reinterpret_cast<float2*>(&Co[(size_t)row0 * N + col]) = v0;
                    *reinterpret_cast<float2*>(&Co[(size_t)(row0 + 8) * N + col]) = v1;
                }
            }
        }
    }
}

// ---------------- fused reduce2 + residual + rms ----------------
__global__ __launch_bounds__(256) void reduce2_rms_kernel(const float* __restrict__ xin,
                                                          const float* __restrict__ w)
{
    const int row = blockIdx.x;
    const int tid = threadIdx.x;
    const float* xr = xin    + (size_t)row * D_SZ;
    const float* p0 = g_part + (size_t)row * D_SZ;
    const float* p1 = g_part + (size_t)(ROWS + row) * D_SZ;
    float* x1r = g_x1 + (size_t)row * D_SZ;

    float vals[4];
    float ss = 0.f;
#pragma unroll
    for (int i = 0; i < 4; i++) {
        const int c = tid + i * 256;
        float v = xr[c] + p0[c] + p1[c];
        x1r[c] = v;
        vals[i] = v;
        ss = fmaf(v, v, ss);
    }
    __shared__ float red[32];
#pragma unroll
    for (int o = 16; o > 0; o >>= 1) ss += __shfl_down_sync(0xffffffffu, ss, o);
    if ((tid & 31) == 0) red[tid >> 5] = ss;
    __syncthreads();
    if (tid < 32) {
        float v = (tid < 8) ? red[tid] : 0.f;
#pragma unroll
        for (int o = 4; o > 0; o >>= 1) v += __shfl_down_sync(0xffffffffu, v, o);
        if (tid == 0) red[0] = v;
    }
    __syncthreads();
    const float inv = rsqrtf(red[0] / (float)D_SZ + 1e-5f);
#pragma unroll
    for (int i = 0; i < 4; i++) {
        const int c = tid + i * 256;
        g_xn[(size_t)row * D_SZ + c] = __float2half_rn(vals[i] * inv * w[c]);
    }
}

// ---------------- split-K=4 reduction ----------------
__global__ void reduce4_kernel(const float* __restrict__ addend,
                               float* __restrict__ out, int n4)
{
    const int i = blockIdx.x * blockDim.x + threadIdx.x;
    if (i >= n4) return;
    float4 v = reinterpret_cast<const float4*>(addend)[i];
#pragma unroll
    for (int z = 0; z < 4; z++) {
        const float4 p = reinterpret_cast<const float4*>(g_part + (size_t)z * ROWS * D_SZ)[i];
        v.x += p.x; v.y += p.y; v.z += p.z; v.w += p.w;
    }
    reinterpret_cast<float4*>(out)[i] = v;
}

// ---------------- fp32 -> fp16 conversion (MLP=4) ----------------
__global__ void cvt_h_kernel(const float* __restrict__ in, __half* __restrict__ out, int n4)
{
    const int stride = gridDim.x * blockDim.x;
    int i = blockIdx.x * blockDim.x + threadIdx.x;
#pragma unroll
    for (int r = 0; r < 4; r++) {
        if (i < n4) {
            float4 v = reinterpret_cast<const float4*>(in)[i];
            __half2 h0 = __floats2half2_rn(v.x, v.y);
            __half2 h1 = __floats2half2_rn(v.z, v.w);
            *reinterpret_cast<uint2*>(out + (size_t)i * 4) =
                make_uint2(*reinterpret_cast<uint32_t*>(&h0), *reinterpret_cast<uint32_t*>(&h1));
        }
        i += stride;
    }
}
#define CVT_GRID(n4) (((n4) + 4 * 256 - 1) / (4 * 256))

// ---------------- causal depthwise conv (k=4) + bias + silu, vectorized ----------------
__global__ __launch_bounds__(544) void conv_silu_kernel(const float* __restrict__ conv_w,
                                                        const float* __restrict__ conv_b)
{
    const int bs = blockIdx.x;          // 0..ROWS-1
    const int s  = bs & (S_SZ - 1);
    const int c  = threadIdx.x * 4;     // channel base, 0..2172

    const float4 w0 = __ldg(reinterpret_cast<const float4*>(conv_w) + (c + 0));
    const float4 w1 = __ldg(reinterpret_cast<const float4*>(conv_w) + (c + 1));
    const float4 w2 = __ldg(reinterpret_cast<const float4*>(conv_w) + (c + 2));
    const float4 w3 = __ldg(reinterpret_cast<const float4*>(conv_w) + (c + 3));
    float4 acc = __ldg(reinterpret_cast<const float4*>(conv_b) + threadIdx.x);

    const float* base = g_zxbcdt + (size_t)bs * D_IN_PROJ + D_INNER + c;
#pragma unroll
    for (int k = 0; k < D_CONV; k++) {
        const int off = k - (D_CONV - 1);        // -3..0
        if (s + off >= 0) {
            const float4 v = *reinterpret_cast<const float4*>(base + (ptrdiff_t)off * D_IN_PROJ);
            acc.x = fmaf(v.x, (&w0.x)[k], acc.x);
            acc.y = fmaf(v.y, (&w1.x)[k], acc.y);
            acc.z = fmaf(v.z, (&w2.x)[k], acc.z);
            acc.w = fmaf(v.w, (&w3.x)[k], acc.w);
        }
    }
    acc.x = silu_f(acc.x);
    acc.y = silu_f(acc.y);
    acc.z = silu_f(acc.z);
    acc.w = silu_f(acc.w);
    *reinterpret_cast<float4*>(g_xbc + (size_t)bs * CONV_DIM + c) = acc;
}

// ---------------- dt/dA packed ----------------
__global__ void dt_kernel(const float* __restrict__ dt_bias,
                          const float* __restrict__ A_log)
{
    const int idx = blockIdx.x * blockDim.x + threadIdx.x;
    if (idx >= ROWS * NHEADS) return;
    const int h = idx & (NHEADS - 1);
    const int r = idx >> 5;
    float x = g_zxbcdt[(size_t)r * D_IN_PROJ + (D_IN_PROJ - NHEADS) + h] + dt_bias[h];
    float dt = (x > 20.f) ? x : log1pf(expf(x));
    g_dtda[idx] = make_float2(dt, expf(-expf(A_log[h]) * dt));
}

// ---------------- SSM scan (round-7 proven config) ----------------
__global__ __launch_bounds__(512, 2) void scan_kernel()
{
    const int pc   = blockIdx.x & 3;
    const int h    = (blockIdx.x >> 2) & (NHEADS - 1);
    const int b    = blockIdx.x >> 7;
    const int w    = threadIdx.x >> 5;
    const int lane = threadIdx.x & 31;
    const int p    = pc * 16 + w;

    const float* rb = g_xbc + (size_t)(b * S_SZ) * CONV_DIM;
    const int xoff = h * HEADDIM + p;
    const float2* dd = g_dtda + (size_t)(b * S_SZ) * NHEADS + h;
    float* yo = g_y + ((size_t)b * S_SZ * NHEADS + h) * HEADDIM + p;

    float h0 = 0.f, h1 = 0.f;

    float2 Bv[2][4], Cv[2][4], Dv[2][4];
    float  Xv[2][4];

    auto ldgrp = [&](int grp, int buf) {
#pragma unroll
        for (int i = 0; i < 4; i++) {
            const int s = grp * 4 + i;
            const float* row = rb + (size_t)s * CONV_DIM;
            Bv[buf][i] = __ldg(reinterpret_cast<const float2*>(row + D_INNER) + lane);
            Cv[buf][i] = __ldg(reinterpret_cast<const float2*>(row + D_INNER + D_STATE) + lane);
            Xv[buf][i] = __ldg(row + xoff);
            Dv[buf][i] = __ldg(dd + (size_t)s * NHEADS);
        }
    };

    ldgrp(0, 0);
    const int NG = S_SZ / 4;
    for (int grp = 0; grp < NG; grp++) {
        const int cur = grp & 1;
        if (grp + 1 < NG) ldgrp(grp + 1, cur ^ 1);

        float part[4];
#pragma unroll
        for (int i = 0; i < 4; i++) {
            const float c = Dv[cur][i].x * Xv[cur][i];
            h0 = fmaf(h0, Dv[cur][i].y, c * Bv[cur][i].x);
            h1 = fmaf(h1, Dv[cur][i].y, c * Bv[cur][i].y);
            part[i] = fmaf(h1, Cv[cur][i].y, h0 * Cv[cur][i].x);
        }
#pragma unroll
        for (int o = 16; o > 0; o >>= 1) {
#pragma unroll
            for (int i = 0; i < 4; i++)
                part[i] += __shfl_xor_sync(0xffffffffu, part[i], o);
        }
        if (lane == 0) {
#pragma unroll
            for (int i = 0; i < 4; i++)
                yo[(size_t)(grp * 4 + i) * (NHEADS * HEADDIM)] = part[i];
        }
    }
}

// ---------------- gate: yg = rms((y + D*xs) * silu(z)) * w  -> fp16 ----------------
__global__ __launch_bounds__(256) void gate_rms_kernel(const float* __restrict__ Dp,
                                                       const float* __restrict__ normw)
{
    const int row = blockIdx.x;
    const int tid = threadIdx.x;

    const float* yr = g_y      + (size_t)row * D_INNER;
    const float* xb = g_xbc    + (size_t)row * CONV_DIM;
    const float* zr = g_zxbcdt + (size_t)row * D_IN_PROJ;

    float vals[8];
    float ss = 0.f;
#pragma unroll
    for (int i = 0; i < 8; i++) {
        const int c = tid + i * 256;
        float v = fmaf(Dp[c >> 6], xb[c], yr[c]);
        v *= silu_f(zr[c]);
        vals[i] = v;
        ss = fmaf(v, v, ss);
    }
    __shared__ float red[32];
#pragma unroll
    for (int o = 16; o > 0; o >>= 1) ss += __shfl_down_sync(0xffffffffu, ss, o);
    if ((tid & 31) == 0) red[tid >> 5] = ss;
    __syncthreads();
    if (tid < 32) {
        float v = (tid < 8) ? red[tid] : 0.f;
#pragma unroll
        for (int o = 4; o > 0; o >>= 1) v += __shfl_down_sync(0xffffffffu, v, o);
        if (tid == 0) red[0] = v;
    }
    __syncthreads();
    const float inv = rsqrtf(red[0] / (float)D_INNER + 1e-5f);
#pragma unroll
    for (int i = 0; i < 8; i++) {
        const int c = tid + i * 256;
        g_yg[(size_t)row * D_INNER + c] = __float2half_rn(vals[i] * inv * normw[c]);
    }
}

// ---------------- GLU (fp16, vectorized) ----------------
__global__ void glu_kernel()
{
    const int idx = blockIdx.x * blockDim.x + threadIdx.x;
    if (idx >= ROWS * H_MLP2 / 2) return;
    const int j2 = idx % (H_MLP2 / 2);
    const int r  = idx / (H_MLP2 / 2);
    const __half2 a2 = *reinterpret_cast<const __half2*>(&g_h1[(size_t)r * H_MLP + j2 * 2]);
    const __half2 g2 = *reinterpret_cast<const __half2*>(&g_h1[(size_t)r * H_MLP + H_MLP2 + j2 * 2]);
    const float2 af = __half22float2(a2);
    const float2 gf = __half22float2(g2);
    *reinterpret_cast<__half2*>(&g_min[(size_t)r * H_MLP2 + j2 * 2]) =
        __floats2half2_rn(af.x * silu_f(gf.x), af.y * silu_f(gf.y));
}

// ---------------- launch ----------------
extern "C" void kernel_launch(void* const* d_in, const int* in_sizes, int n_in,
                              void* d_out, int out_size)
{
    const float* x          = (const float*)d_in[0];
    const float* in_proj_w  = (const float*)d_in[1];
    const float* conv_w     = (const float*)d_in[2];
    const float* conv_b     = (const float*)d_in[3];
    const float* dt_bias    = (const float*)d_in[4];
    const float* A_log      = (const float*)d_in[5];
    const float* Dp         = (const float*)d_in[6];
    const float* ssm_norm_w = (const float*)d_in[7];
    const float* out_proj_w = (const float*)d_in[8];
    const float* rms_w      = (const float*)d_in[9];
    const float* fc1_w      = (const float*)d_in[10];
    const float* fc2_w      = (const float*)d_in[11];
    float* out = (float*)d_out;

    float *p_zx, *p_x1, *p_part;
    __half *p_h1, *p_xh, *p_wip, *p_wop, *p_wf1, *p_wf2, *p_yg, *p_xn, *p_min;
    cudaGetSymbolAddress((void**)&p_zx,  g_zxbcdt);
    cudaGetSymbolAddress((void**)&p_x1,  g_x1);
    cudaGetSymbolAddress((void**)&p_part, g_part);
    cudaGetSymbolAddress((void**)&p_h1,  g_h1);
    cudaGetSymbolAddress((void**)&p_xh,  g_xh);
    cudaGetSymbolAddress((void**)&p_wip, g_wip);
    cudaGetSymbolAddress((void**)&p_wop, g_wop);
    cudaGetSymbolAddress((void**)&p_wf1, g_wf1);
    cudaGetSymbolAddress((void**)&p_wf2, g_wf2);
    cudaGetSymbolAddress((void**)&p_yg,  g_yg);
    cudaGetSymbolAddress((void**)&p_xn,  g_xn);
    cudaGetSymbolAddress((void**)&p_min, g_min);

    cudaFuncSetAttribute(hgemm_kernel<0>,
                         cudaFuncAttributeMaxDynamicSharedMemorySize, GEMM_SMEM_BYTES);
    cudaFuncSetAttribute(hgemm_kernel<1>,
                         cudaFuncAttributeMaxDynamicSharedMemorySize, GEMM_SMEM_BYTES);

    // in_proj is our 4th launch so ncu (-s 5 -c 1) profiles it.
    cvt_h_kernel<<<CVT_GRID(ROWS * D_SZ / 4), 256>>>(x, p_xh, ROWS * D_SZ / 4);                  // 1
    cvt_h_kernel<<<CVT_GRID(D_IN_PROJ * D_SZ / 4), 256>>>(in_proj_w, p_wip, D_IN_PROJ * D_SZ / 4); // 2
    cvt_h_kernel<<<CVT_GRID(D_SZ * D_INNER / 4), 256>>>(out_proj_w, p_wop, D_SZ * D_INNER / 4);    // 3

    // 4) in_proj: zxbcdt[2048,4256] = xh @ wip^T
    {
        dim3 grid((D_IN_PROJ + 127) / 128, ROWS / 128, 1);
        hgemm_kernel<0><<<grid, 256, GEMM_SMEM_BYTES>>>(p_xh, p_wip, nullptr, p_zx,
                                                        ROWS, D_IN_PROJ, D_SZ, D_SZ);
    }

    cvt_h_kernel<<<CVT_GRID(H_MLP * D_SZ / 4), 256>>>(fc1_w, p_wf1, H_MLP * D_SZ / 4);           // 5
    cvt_h_kernel<<<CVT_GRID(D_SZ * H_MLP2 / 4), 256>>>(fc2_w, p_wf2, D_SZ * H_MLP2 / 4);         // 6

    // dt/dA (packed)
    dt_kernel<<<(ROWS * NHEADS + 255) / 256, 256>>>(dt_bias, A_log);
    // conv + silu (vectorized, no division)
    conv_silu_kernel<<<ROWS, CONV_DIM / 4>>>(conv_w, conv_b);
    // scan
    scan_kernel<<<B_SZ * NHEADS * 4, 512>>>();
    // gate + rms(ssm_norm)
    gate_rms_kernel<<<ROWS, 256>>>(Dp, ssm_norm_w);
    // out_proj split-K=2, then fused: x1 = x + p0 + p1, xn = rms(x1)*w
    {
        dim3 grid(D_SZ / 128, ROWS / 128, 2);
        hgemm_kernel<0><<<grid, 256, GEMM_SMEM_BYTES>>>(p_yg, p_wop, nullptr, p_part,
                                                        ROWS, D_SZ, D_INNER, D_INNER / 2);
        reduce2_rms_kernel<<<ROWS, 256>>>(x, rms_w);
    }
    // fc1: h1 = xn @ wf1^T  (fp16 output)
    {
        dim3 grid(H_MLP / 128, ROWS / 128, 1);
        hgemm_kernel<1><<<grid, 256, GEMM_SMEM_BYTES>>>(p_xn, p_wf1, nullptr, p_h1,
                                                        ROWS, H_MLP, D_SZ, D_SZ);
    }
    // GLU (fp16, vectorized)
    glu_kernel<<<(ROWS * H_MLP2 / 2 + 255) / 256, 256>>>();
    // fc2 split-K=4, then out = x1 + sum parts
    {
        dim3 grid(D_SZ / 128, ROWS / 128, 4);
        hgemm_kernel<0><<<grid, 256, GEMM_SMEM_BYTES>>>(p_min, p_wf2, nullptr, p_part,
                                                        ROWS, D_SZ, H_MLP2, H_MLP2 / 4);
        reduce4_kernel<<<(ROWS * D_SZ / 4 + 255) / 256, 256>>>(p_x1, out, ROWS * D_SZ / 4);
    }
}

// round 17
// speedup vs baseline: 1.0223x; 1.0067x over previous
#include <cuda_runtime.h>
#include <cuda_fp16.h>
#include <cstdint>
#include <cstdio>

// ---------------- problem constants ----------------
#define B_SZ 2
#define S_SZ 1024
#define D_SZ 1024
#define D_INNER 2048
#define HEADDIM 64
#define NHEADS 32
#define D_STATE 64
#define D_CONV 4
#define CONV_DIM (D_INNER + 2 * D_STATE)                 // 2176
#define D_IN_PROJ (2 * D_INNER + 2 * D_STATE + NHEADS)   // 4256
#define H_MLP 8192
#define H_MLP2 4096
#define ROWS (B_SZ * S_SZ)                               // 2048

// ---------------- scratch (device globals; no allocation allowed) ----------------
__device__ float g_zxbcdt[ROWS * D_IN_PROJ];
__device__ float g_xbc[ROWS * CONV_DIM];
__device__ float2 g_dtda[ROWS * NHEADS];
__device__ float g_y[ROWS * D_INNER];
__device__ float g_x1[ROWS * D_SZ];
__device__ float g_part[4 * ROWS * D_SZ];
// fp16 buffers
__device__ __half g_h1[ROWS * H_MLP];
__device__ __half g_xh [ROWS * D_SZ];
__device__ __half g_wip[D_IN_PROJ * D_SZ];
__device__ __half g_wop[D_SZ * D_INNER];
__device__ __half g_wf1[H_MLP * D_SZ];
__device__ __half g_wf2[D_SZ * H_MLP2];
__device__ __half g_yg [ROWS * D_INNER];
__device__ __half g_xn [ROWS * D_SZ];
__device__ __half g_min[ROWS * H_MLP2];

__device__ __forceinline__ float silu_f(float v) {
    return v / (1.f + __expf(-v));
}
__device__ __forceinline__ uint32_t smem_u32(const void* p) {
    uint32_t a;
    asm("{ .reg .u64 t; cvta.to.shared.u64 t, %1; cvt.u32.u64 %0, t; }" : "=r"(a) : "l"(p));
    return a;
}
__device__ __forceinline__ void cp_async16(uint32_t dst, const void* src) {
    asm volatile("cp.async.cg.shared.global [%0], [%1], 16;" :: "r"(dst), "l"(src));
}
#define CP_COMMIT() asm volatile("cp.async.commit_group;" ::: "memory")
#define CP_WAIT(n)  asm volatile("cp.async.wait_group %0;" :: "n"(n) : "memory")

#define HPITCHW 20
#define ASTGW (128 * HPITCHW)
#define STGW  (2 * ASTGW)
#define NSTG  4
#define GEMM_SMEM_BYTES (NSTG * STGW * 4)   // 81920

// ---------------- pipelined fp16 mma.sync GEMM (128x128, optional split-K) ----------------
template <int HOUT>
__global__ __launch_bounds__(256, 2) void hgemm_kernel(
    const __half* __restrict__ A, const __half* __restrict__ W,
    const float* __restrict__ addend, void* __restrict__ Cv_,
    int M, int N, int K, int kchunk)
{
    extern __shared__ uint32_t sm[];
    const uint32_t sb = smem_u32(sm);

    const int tid = threadIdx.x;
    const int bm = blockIdx.y * 128;
    const int bn = blockIdx.x * 128;
    const int kbeg = blockIdx.z * kchunk;
    const bool partial = (gridDim.z > 1);

    const int warp = tid >> 5;
    const int lane = tid & 31;
    const int g  = lane >> 2;
    const int t4 = lane & 3;
    const int warp_m = (warp >> 2) * 64;
    const int warp_n = (warp & 3) * 32;

    const uint32_t a_off =
        ((uint32_t)(warp_m + (lane & 7) + ((lane >> 3) & 1) * 8) * HPITCHW
         + ((lane >> 4) & 1) * 4) * 4;
    const uint32_t b_off4 =
        ((uint32_t)(warp_n + (lane & 7) + ((lane >> 4) & 1) * 8) * HPITCHW
         + ((lane >> 3) & 1) * 4) * 4;

    const int lr = tid >> 2;
    const int q  = tid & 3;

    const __half* Ap0 = A + (size_t)(bm + lr) * K + kbeg + q * 8;
    const __half* Ap1 = A + (size_t)(bm + 64 + lr) * K + kbeg + q * 8;
    int wr0 = bn + lr;      if (wr0 > N - 1) wr0 = N - 1;
    int wr1 = bn + 64 + lr; if (wr1 > N - 1) wr1 = N - 1;
    const __half* Wp0 = W + (size_t)wr0 * K + kbeg + q * 8;
    const __half* Wp1 = W + (size_t)wr1 * K + kbeg + q * 8;

    const uint32_t d0 = (uint32_t)lr * 80 + q * 16;
    const uint32_t d1 = d0 + 64 * 80;
    const int T = kchunk / 32;

    float acc[4][4][4];
#pragma unroll
    for (int i = 0; i < 4; i++)
#pragma unroll
        for (int j = 0; j < 4; j++)
#pragma unroll
            for (int r = 0; r < 4; r++) acc[i][j][r] = 0.f;

    auto load_stage = [&](int j) {
        if (j < T) {
            const uint32_t base = sb + (j & (NSTG - 1)) * (STGW * 4);
            const int ko = j * 32;
            cp_async16(base + d0, Ap0 + ko);
            cp_async16(base + d1, Ap1 + ko);
            cp_async16(base + ASTGW * 4 + d0, Wp0 + ko);
            cp_async16(base + ASTGW * 4 + d1, Wp1 + ko);
        }
        CP_COMMIT();
    };

    load_stage(0);
    load_stage(1);
    load_stage(2);

    for (int kt = 0; kt < T; kt++) {
        CP_WAIT(2);
        __syncthreads();
        load_stage(kt + 3);

        const uint32_t sA = sb + (kt & (NSTG - 1)) * (STGW * 4);
        const uint32_t sB = sA + ASTGW * 4;
#pragma unroll
        for (int kw = 0; kw < 16; kw += 8) {
            uint32_t af[4][4];
            uint32_t bf[4][2];
#pragma unroll
            for (int mt = 0; mt < 4; mt++) {
                const uint32_t addr = sA + a_off + (uint32_t)(mt * 16 * HPITCHW + kw) * 4;
                asm volatile(
                    "ldmatrix.sync.aligned.m8n8.x4.shared.b16 {%0,%1,%2,%3}, [%4];"
                    : "=r"(af[mt][0]), "=r"(af[mt][1]), "=r"(af[mt][2]), "=r"(af[mt][3])
                    : "r"(addr));
            }
#pragma unroll
            for (int ntp = 0; ntp < 2; ntp++) {
                const uint32_t addr = sB + b_off4 + (uint32_t)(ntp * 16 * HPITCHW + kw) * 4;
                asm volatile(
                    "ldmatrix.sync.aligned.m8n8.x4.shared.b16 {%0,%1,%2,%3}, [%4];"
                    : "=r"(bf[2 * ntp][0]), "=r"(bf[2 * ntp][1]),
                      "=r"(bf[2 * ntp + 1][0]), "=r"(bf[2 * ntp + 1][1])
                    : "r"(addr));
            }
#pragma unroll
            for (int mt = 0; mt < 4; mt++)
#pragma unroll
                for (int nt = 0; nt < 4; nt++) {
                    asm volatile(
                        "mma.sync.aligned.m16n8k16.row.col.f32.f16.f16.f32 "
                        "{%0,%1,%2,%3}, {%4,%5,%6,%7}, {%8,%9}, {%0,%1,%2,%3};"
                        : "+f"(acc[mt][nt][0]), "+f"(acc[mt][nt][1]),
                          "+f"(acc[mt][nt][2]), "+f"(acc[mt][nt][3])
                        : "r"(af[mt][0]), "r"(af[mt][1]), "r"(af[mt][2]), "r"(af[mt][3]),
                          "r"(bf[nt][0]), "r"(bf[nt][1]));
                }
        }
    }

#pragma unroll
    for (int mt = 0; mt < 4; mt++) {
        const int row0 = bm + warp_m + mt * 16 + g;
#pragma unroll
        for (int nt = 0; nt < 4; nt++) {
            const int col = bn + warp_n + nt * 8 + 2 * t4;
            if (col < N) {
                if (HOUT) {
                    __half* Ch = (__half*)Cv_;
                    *reinterpret_cast<__half2*>(&Ch[(size_t)row0 * N + col]) =
                        __floats2half2_rn(acc[mt][nt][0], acc[mt][nt][1]);
                    *reinterpret_cast<__half2*>(&Ch[(size_t)(row0 + 8) * N + col]) =
                        __floats2half2_rn(acc[mt][nt][2], acc[mt][nt][3]);
                } else {
                    float* Cf = (float*)Cv_;
                    float* Co = partial ? (Cf + (size_t)blockIdx.z * M * N) : Cf;
                    float2 v0 = make_float2(acc[mt][nt][0], acc[mt][nt][1]);
                    float2 v1 = make_float2(acc[mt][nt][2], acc[mt][nt][3]);
                    if (!partial && addend) {
                        const float2 a0 = *reinterpret_cast<const float2*>(&addend[(size_t)row0 * N + col]);
                        const float2 a1 = *reinterpret_cast<const float2*>(&addend[(size_t)(row0 + 8) * N + col]);
                        v0.x += a0.x; v0.y += a0.y;
                        v1.x += a1.x; v1.y += a1.y;
                    }
                    *reinterpret_cast<float2*>(&Co[(size_t)row0 * N + col]) = v0;
                    *reinterpret_cast<float2*>(&Co[(size_t)(row0 + 8) * N + col]) = v1;
                }
            }
        }
    }
}

// ---------------- fused reduce2 + residual + rms ----------------
__global__ __launch_bounds__(256) void reduce2_rms_kernel(const float* __restrict__ xin,
                                                          const float* __restrict__ w)
{
    const int row = blockIdx.x;
    const int tid = threadIdx.x;
    const float* xr = xin    + (size_t)row * D_SZ;
    const float* p0 = g_part + (size_t)row * D_SZ;
    const float* p1 = g_part + (size_t)(ROWS + row) * D_SZ;
    float* x1r = g_x1 + (size_t)row * D_SZ;

    float vals[4];
    float ss = 0.f;
#pragma unroll
    for (int i = 0; i < 4; i++) {
        const int c = tid + i * 256;
        float v = xr[c] + p0[c] + p1[c];
        x1r[c] = v;
        vals[i] = v;
        ss = fmaf(v, v, ss);
    }
    __shared__ float red[32];
#pragma unroll
    for (int o = 16; o > 0; o >>= 1) ss += __shfl_down_sync(0xffffffffu, ss, o);
    if ((tid & 31) == 0) red[tid >> 5] = ss;
    __syncthreads();
    if (tid < 32) {
        float v = (tid < 8) ? red[tid] : 0.f;
#pragma unroll
        for (int o = 4; o > 0; o >>= 1) v += __shfl_down_sync(0xffffffffu, v, o);
        if (tid == 0) red[0] = v;
    }
    __syncthreads();
    const float inv = rsqrtf(red[0] / (float)D_SZ + 1e-5f);
#pragma unroll
    for (int i = 0; i < 4; i++) {
        const int c = tid + i * 256;
        g_xn[(size_t)row * D_SZ + c] = __float2half_rn(vals[i] * inv * w[c]);
    }
}

// ---------------- split-K=4 reduction ----------------
__global__ void reduce4_kernel(const float* __restrict__ addend,
                               float* __restrict__ out, int n4)
{
    const int i = blockIdx.x * blockDim.x + threadIdx.x;
    if (i >= n4) return;
    float4 v = reinterpret_cast<const float4*>(addend)[i];
#pragma unroll
    for (int z = 0; z < 4; z++) {
        const float4 p = reinterpret_cast<const float4*>(g_part + (size_t)z * ROWS * D_SZ)[i];
        v.x += p.x; v.y += p.y; v.z += p.z; v.w += p.w;
    }
    reinterpret_cast<float4*>(out)[i] = v;
}

// ---------------- one-shot fp32 -> fp16 conversion of ALL operands ----------------
// segment boundaries (in float4 units)
#define S0 (ROWS * D_SZ / 4)                       // x
#define S1 (S0 + D_IN_PROJ * D_SZ / 4)             // in_proj_w
#define S2 (S1 + D_SZ * D_INNER / 4)               // out_proj_w
#define S3 (S2 + H_MLP * D_SZ / 4)                 // fc1_w
#define S4 (S3 + D_SZ * H_MLP2 / 4)                // fc2_w  (total)

__global__ void cvt_all_kernel(const float* __restrict__ x,
                               const float* __restrict__ wip,
                               const float* __restrict__ wop,
                               const float* __restrict__ wf1,
                               const float* __restrict__ wf2)
{
    const int stride = gridDim.x * blockDim.x;
    int i = blockIdx.x * blockDim.x + threadIdx.x;
#pragma unroll
    for (int r = 0; r < 4; r++) {
        if (i < S4) {
            const float* in;
            __half* out;
            int j;
            if (i < S0)      { in = x;   out = g_xh;  j = i; }
            else if (i < S1) { in = wip; out = g_wip; j = i - S0; }
            else if (i < S2) { in = wop; out = g_wop; j = i - S1; }
            else if (i < S3) { in = wf1; out = g_wf1; j = i - S2; }
            else             { in = wf2; out = g_wf2; j = i - S3; }
            float4 v = reinterpret_cast<const float4*>(in)[j];
            __half2 h0 = __floats2half2_rn(v.x, v.y);
            __half2 h1 = __floats2half2_rn(v.z, v.w);
            *reinterpret_cast<uint2*>(out + (size_t)j * 4) =
                make_uint2(*reinterpret_cast<uint32_t*>(&h0), *reinterpret_cast<uint32_t*>(&h1));
        }
        i += stride;
    }
}

// ---------------- causal depthwise conv + bias + silu + dt/dA (fused) ----------------
// grid = ROWS blocks, 544 threads; threads 0..543 do conv (4 channels each),
// threads 0..31 additionally compute dt/dA for their head.
__global__ __launch_bounds__(544) void conv_dt_kernel(const float* __restrict__ conv_w,
                                                      const float* __restrict__ conv_b,
                                                      const float* __restrict__ dt_bias,
                                                      const float* __restrict__ A_log)
{
    const int bs = blockIdx.x;          // 0..ROWS-1
    const int s  = bs & (S_SZ - 1);
    const int c  = threadIdx.x * 4;

    const float4 w0 = __ldg(reinterpret_cast<const float4*>(conv_w) + (c + 0));
    const float4 w1 = __ldg(reinterpret_cast<const float4*>(conv_w) + (c + 1));
    const float4 w2 = __ldg(reinterpret_cast<const float4*>(conv_w) + (c + 2));
    const float4 w3 = __ldg(reinterpret_cast<const float4*>(conv_w) + (c + 3));
    float4 acc = __ldg(reinterpret_cast<const float4*>(conv_b) + threadIdx.x);

    const float* base = g_zxbcdt + (size_t)bs * D_IN_PROJ + D_INNER + c;
#pragma unroll
    for (int k = 0; k < D_CONV; k++) {
        const int off = k - (D_CONV - 1);
        if (s + off >= 0) {
            const float4 v = *reinterpret_cast<const float4*>(base + (ptrdiff_t)off * D_IN_PROJ);
            acc.x = fmaf(v.x, (&w0.x)[k], acc.x);
            acc.y = fmaf(v.y, (&w1.x)[k], acc.y);
            acc.z = fmaf(v.z, (&w2.x)[k], acc.z);
            acc.w = fmaf(v.w, (&w3.x)[k], acc.w);
        }
    }
    acc.x = silu_f(acc.x);
    acc.y = silu_f(acc.y);
    acc.z = silu_f(acc.z);
    acc.w = silu_f(acc.w);
    *reinterpret_cast<float4*>(g_xbc + (size_t)bs * CONV_DIM + c) = acc;

    if (threadIdx.x < NHEADS) {
        const int h = threadIdx.x;
        float xx = g_zxbcdt[(size_t)bs * D_IN_PROJ + (D_IN_PROJ - NHEADS) + h] + dt_bias[h];
        float dt = (xx > 20.f) ? xx : log1pf(expf(xx));
        g_dtda[bs * NHEADS + h] = make_float2(dt, expf(-expf(A_log[h]) * dt));
    }
}

// ---------------- SSM scan (round-7 proven config) ----------------
__global__ __launch_bounds__(512, 2) void scan_kernel()
{
    const int pc   = blockIdx.x & 3;
    const int h    = (blockIdx.x >> 2) & (NHEADS - 1);
    const int b    = blockIdx.x >> 7;
    const int w    = threadIdx.x >> 5;
    const int lane = threadIdx.x & 31;
    const int p    = pc * 16 + w;

    const float* rb = g_xbc + (size_t)(b * S_SZ) * CONV_DIM;
    const int xoff = h * HEADDIM + p;
    const float2* dd = g_dtda + (size_t)(b * S_SZ) * NHEADS + h;
    float* yo = g_y + ((size_t)b * S_SZ * NHEADS + h) * HEADDIM + p;

    float h0 = 0.f, h1 = 0.f;

    float2 Bv[2][4], Cv[2][4], Dv[2][4];
    float  Xv[2][4];

    auto ldgrp = [&](int grp, int buf) {
#pragma unroll
        for (int i = 0; i < 4; i++) {
            const int s = grp * 4 + i;
            const float* row = rb + (size_t)s * CONV_DIM;
            Bv[buf][i] = __ldg(reinterpret_cast<const float2*>(row + D_INNER) + lane);
            Cv[buf][i] = __ldg(reinterpret_cast<const float2*>(row + D_INNER + D_STATE) + lane);
            Xv[buf][i] = __ldg(row + xoff);
            Dv[buf][i] = __ldg(dd + (size_t)s * NHEADS);
        }
    };

    ldgrp(0, 0);
    const int NG = S_SZ / 4;
    for (int grp = 0; grp < NG; grp++) {
        const int cur = grp & 1;
        if (grp + 1 < NG) ldgrp(grp + 1, cur ^ 1);

        float part[4];
#pragma unroll
        for (int i = 0; i < 4; i++) {
            const float c = Dv[cur][i].x * Xv[cur][i];
            h0 = fmaf(h0, Dv[cur][i].y, c * Bv[cur][i].x);
            h1 = fmaf(h1, Dv[cur][i].y, c * Bv[cur][i].y);
            part[i] = fmaf(h1, Cv[cur][i].y, h0 * Cv[cur][i].x);
        }
#pragma unroll
        for (int o = 16; o > 0; o >>= 1) {
#pragma unroll
            for (int i = 0; i < 4; i++)
                part[i] += __shfl_xor_sync(0xffffffffu, part[i], o);
        }
        if (lane == 0) {
#pragma unroll
            for (int i = 0; i < 4; i++)
                yo[(size_t)(grp * 4 + i) * (NHEADS * HEADDIM)] = part[i];
        }
    }
}

// ---------------- gate: yg = rms((y + D*xs) * silu(z)) * w  -> fp16 ----------------
__global__ __launch_bounds__(256) void gate_rms_kernel(const float* __restrict__ Dp,
                                                       const float* __restrict__ normw)
{
    const int row = blockIdx.x;
    const int tid = threadIdx.x;

    const float* yr = g_y      + (size_t)row * D_INNER;
    const float* xb = g_xbc    + (size_t)row * CONV_DIM;
    const float* zr = g_zxbcdt + (size_t)row * D_IN_PROJ;

    float vals[8];
    float ss = 0.f;
#pragma unroll
    for (int i = 0; i < 8; i++) {
        const int c = tid + i * 256;
        float v = fmaf(Dp[c >> 6], xb[c], yr[c]);
        v *= silu_f(zr[c]);
        vals[i] = v;
        ss = fmaf(v, v, ss);
    }
    __shared__ float red[32];
#pragma unroll
    for (int o = 16; o > 0; o >>= 1) ss += __shfl_down_sync(0xffffffffu, ss, o);
    if ((tid & 31) == 0) red[tid >> 5] = ss;
    __syncthreads();
    if (tid < 32) {
        float v = (tid < 8) ? red[tid] : 0.f;
#pragma unroll
        for (int o = 4; o > 0; o >>= 1) v += __shfl_down_sync(0xffffffffu, v, o);
        if (tid == 0) red[0] = v;
    }
    __syncthreads();
    const float inv = rsqrtf(red[0] / (float)D_INNER + 1e-5f);
#pragma unroll
    for (int i = 0; i < 8; i++) {
        const int c = tid + i * 256;
        g_yg[(size_t)row * D_INNER + c] = __float2half_rn(vals[i] * inv * normw[c]);
    }
}

// ---------------- GLU (fp16, vectorized) ----------------
__global__ void glu_kernel()
{
    const int idx = blockIdx.x * blockDim.x + threadIdx.x;
    if (idx >= ROWS * H_MLP2 / 2) return;
    const int j2 = idx % (H_MLP2 / 2);
    const int r  = idx / (H_MLP2 / 2);
    const __half2 a2 = *reinterpret_cast<const __half2*>(&g_h1[(size_t)r * H_MLP + j2 * 2]);
    const __half2 g2 = *reinterpret_cast<const __half2*>(&g_h1[(size_t)r * H_MLP + H_MLP2 + j2 * 2]);
    const float2 af = __half22float2(a2);
    const float2 gf = __half22float2(g2);
    *reinterpret_cast<__half2*>(&g_min[(size_t)r * H_MLP2 + j2 * 2]) =
        __floats2half2_rn(af.x * silu_f(gf.x), af.y * silu_f(gf.y));
}

// ---------------- launch ----------------
extern "C" void kernel_launch(void* const* d_in, const int* in_sizes, int n_in,
                              void* d_out, int out_size)
{
    const float* x          = (const float*)d_in[0];
    const float* in_proj_w  = (const float*)d_in[1];
    const float* conv_w     = (const float*)d_in[2];
    const float* conv_b     = (const float*)d_in[3];
    const float* dt_bias    = (const float*)d_in[4];
    const float* A_log      = (const float*)d_in[5];
    const float* Dp         = (const float*)d_in[6];
    const float* ssm_norm_w = (const float*)d_in[7];
    const float* out_proj_w = (const float*)d_in[8];
    const float* rms_w      = (const float*)d_in[9];
    const float* fc1_w      = (const float*)d_in[10];
    const float* fc2_w      = (const float*)d_in[11];
    float* out = (float*)d_out;

    float *p_zx, *p_x1, *p_part;
    __half *p_h1, *p_xh, *p_wip, *p_wop, *p_wf1, *p_wf2, *p_yg, *p_xn, *p_min;
    cudaGetSymbolAddress((void**)&p_zx,  g_zxbcdt);
    cudaGetSymbolAddress((void**)&p_x1,  g_x1);
    cudaGetSymbolAddress((void**)&p_part, g_part);
    cudaGetSymbolAddress((void**)&p_h1,  g_h1);
    cudaGetSymbolAddress((void**)&p_xh,  g_xh);
    cudaGetSymbolAddress((void**)&p_wip, g_wip);
    cudaGetSymbolAddress((void**)&p_wop, g_wop);
    cudaGetSymbolAddress((void**)&p_wf1, g_wf1);
    cudaGetSymbolAddress((void**)&p_wf2, g_wf2);
    cudaGetSymbolAddress((void**)&p_yg,  g_yg);
    cudaGetSymbolAddress((void**)&p_xn,  g_xn);
    cudaGetSymbolAddress((void**)&p_min, g_min);

    cudaFuncSetAttribute(hgemm_kernel<0>,
                         cudaFuncAttributeMaxDynamicSharedMemorySize, GEMM_SMEM_BYTES);
    cudaFuncSetAttribute(hgemm_kernel<1>,
                         cudaFuncAttributeMaxDynamicSharedMemorySize, GEMM_SMEM_BYTES);

    // 1) convert all fp16 operands in ONE launch
    cvt_all_kernel<<<(S4 + 4 * 256 - 1) / (4 * 256), 256>>>(x, in_proj_w, out_proj_w, fc1_w, fc2_w);

    // 2) in_proj: zxbcdt[2048,4256] = xh @ wip^T
    {
        dim3 grid((D_IN_PROJ + 127) / 128, ROWS / 128, 1);
        hgemm_kernel<0><<<grid, 256, GEMM_SMEM_BYTES>>>(p_xh, p_wip, nullptr, p_zx,
                                                        ROWS, D_IN_PROJ, D_SZ, D_SZ);
    }
    // 3) conv + silu + dt/dA (fused)
    conv_dt_kernel<<<ROWS, CONV_DIM / 4>>>(conv_w, conv_b, dt_bias, A_log);
    // 4) scan  (this is our 4th launch -> ncu profiles it)
    scan_kernel<<<B_SZ * NHEADS * 4, 512>>>();
    // 5) gate + rms(ssm_norm)
    gate_rms_kernel<<<ROWS, 256>>>(Dp, ssm_norm_w);
    // 6) out_proj split-K=2, then fused: x1 = x + p0 + p1, xn = rms(x1)*w
    {
        dim3 grid(D_SZ / 128, ROWS / 128, 2);
        hgemm_kernel<0><<<grid, 256, GEMM_SMEM_BYTES>>>(p_yg, p_wop, nullptr, p_part,
                                                        ROWS, D_SZ, D_INNER, D_INNER / 2);
        reduce2_rms_kernel<<<ROWS, 256>>>(x, rms_w);
    }
    // 7) fc1: h1 = xn @ wf1^T  (fp16 output)
    {
        dim3 grid(H_MLP / 128, ROWS / 128, 1);
        hgemm_kernel<1><<<grid, 256, GEMM_SMEM_BYTES>>>(p_xn, p_wf1, nullptr, p_h1,
                                                        ROWS, H_MLP, D_SZ, D_SZ);
    }
    // 8) GLU (fp16, vectorized)
    glu_kernel<<<(ROWS * H_MLP2 / 2 + 255) / 256, 256>>>();
    // 9) fc2 split-K=4, then out = x1 + sum parts
    {
        dim3 grid(D_SZ / 128, ROWS / 128, 4);
        hgemm_kernel<0><<<grid, 256, GEMM_SMEM_BYTES>>>(p_min, p_wf2, nullptr, p_part,
                                                        ROWS, D_SZ, H_MLP2, H_MLP2 / 4);
        reduce4_kernel<<<(ROWS * D_SZ / 4 + 255) / 256, 256>>>(p_x1, out, ROWS * D_SZ / 4);
    }
}